// round 12
// baseline (speedup 1.0000x reference)
#include <cuda_runtime.h>
#include <math.h>
#include <float.h>

// layers: C = {64,128,256,512}, HW = {3136,784,196,49}, B=256, R=2000
#define NB 256
#define NR 2000
#define NRP 2048

__constant__ int c_C[4]    = {64, 128, 256, 512};
__constant__ int c_qoff[4] = {0, 16384, 49152, 114688};

// scratch (static device globals; no allocation)
__device__ __align__(16) float g_fq[245760];        // pooled queries
__device__ __align__(16) float g_dot[4 * NB * NRP]; // q . ref^T, padded
__device__ float g_r2[4 * NR];
__device__ float g_q2[4 * NB];
__device__ float g_lid[NB * 4];

// ---- stream + events for pool/gemm overlap (created once, before any capture;
//      no device-memory allocation involved) ----
struct OverlapRes {
    cudaStream_t side;
    cudaEvent_t  evp[4];   // pool(layer) done
    cudaEvent_t  evb;      // all gemms done
    OverlapRes() {
        cudaStreamCreateWithFlags(&side, cudaStreamNonBlocking);
        for (int i = 0; i < 4; i++)
            cudaEventCreateWithFlags(&evp[i], cudaEventDisableTiming);
        cudaEventCreateWithFlags(&evb, cudaEventDisableTiming);
    }
};
static OverlapRes g_ov;

// ---------------- kernel 1: per-layer spatial mean pooling (warp per row) ----------------
__global__ void __launch_bounds__(256) pool_layer_kernel(
    const float* __restrict__ f, int HW, int qoff, int nrows, float inv, int vec)
{
    int gw   = (blockIdx.x * 256 + threadIdx.x) >> 5;
    int lane = threadIdx.x & 31;
    if (gw >= nrows) return;
    const float* src = f + (size_t)gw * HW;

    float s = 0.f;
    if (vec) {
        const float4* s4 = (const float4*)src;
        int n4 = HW >> 2;
        #pragma unroll 4
        for (int i = lane; i < n4; i += 32) {
            float4 v = s4[i];
            s += (v.x + v.y) + (v.z + v.w);
        }
    } else {
        #pragma unroll 2
        for (int i = lane; i < HW; i += 32) s += src[i];
    }
    #pragma unroll
    for (int o = 16; o > 0; o >>= 1) s += __shfl_xor_sync(0xffffffffu, s, o);
    if (lane == 0) g_fq[qoff + gw] = s * inv;
}

// ---------------- kernel 2: squared norms (unchanged) ----------------
__global__ void __launch_bounds__(256) norms_kernel(
    const float* __restrict__ r0, const float* __restrict__ r1,
    const float* __restrict__ r2, const float* __restrict__ r3)
{
    int gw   = (blockIdx.x * 256 + threadIdx.x) >> 5;
    int lane = threadIdx.x & 31;
    if (gw >= 9024) return;

    const float* src;
    float* out;
    int C;
    if (gw < 8000) {
        int l = gw / NR, row = gw % NR;
        const float* rp = (l == 0) ? r0 : (l == 1) ? r1 : (l == 2) ? r2 : r3;
        C = c_C[l];
        src = rp + (size_t)row * C;
        out = g_r2 + l * NR + row;
    } else {
        int idx = gw - 8000;
        int l = idx >> 8, row = idx & 255;
        C = c_C[l];
        src = g_fq + c_qoff[l] + (size_t)row * C;
        out = g_q2 + l * NB + row;
    }
    float s = 0.f;
    const float4* s4 = (const float4*)src;
    int n4 = C >> 2;
    #pragma unroll 4
    for (int i = lane; i < n4; i += 32) {
        float4 v = s4[i];
        s += v.x * v.x + v.y * v.y + v.z * v.z + v.w * v.w;
    }
    #pragma unroll
    for (int o = 16; o > 0; o >>= 1) s += __shfl_xor_sync(0xffffffffu, s, o);
    if (lane == 0) *out = s;
}

// ---------------- kernel 3: 128x64 tile, 256 threads, 8x4 acc (R10), per-layer ----------------
__global__ void __launch_bounds__(256) dist_gemm_kernel(
    const float* __restrict__ ref, int l)
{
    int C = c_C[l];
    const float* q = g_fq + c_qoff[l];

    int bt = blockIdx.y << 7;   // batch tile (128)
    int rt = blockIdx.x << 6;   // ref tile (64)

    __shared__ __align__(16) float qs[2][16][132];
    __shared__ __align__(16) float rs[2][16][68];

    int tx = threadIdx.x;
    int ty = threadIdx.y;
    int tid = ty * 16 + tx;

    int isR  = tid >> 7;
    int qrow = tid & 127;
    int rrow = (tid & 127) >> 1;
    int rkg  = tid & 1;

    const float* gsrc;
    size_t gbase;
    int valid;
    if (isR) {
        int rr = rt + rrow;
        valid = (rr < NR);
        gbase = (size_t)(valid ? rr : 0) * C;
        gsrc  = ref;
    } else {
        valid = 1;
        gbase = (size_t)(bt + qrow) * C;
        gsrc  = q;
    }
    float* sq0 = &qs[0][0][0] + qrow;
    float* sq1 = &qs[1][0][0] + qrow;
    float* sr0 = &rs[0][0][0] + rrow;
    float* sr1 = &rs[1][0][0] + rrow;

    float acc[8][4];
    #pragma unroll
    for (int i = 0; i < 8; i++)
        #pragma unroll
        for (int j = 0; j < 4; j++) acc[i][j] = 0.f;

    if (!isR) {
        #pragma unroll
        for (int g = 0; g < 4; g++) {
            float4 v = *(const float4*)&gsrc[gbase + g * 4];
            sq0[(g * 4 + 0) * 132] = v.x;
            sq0[(g * 4 + 1) * 132] = v.y;
            sq0[(g * 4 + 2) * 132] = v.z;
            sq0[(g * 4 + 3) * 132] = v.w;
        }
    } else {
        #pragma unroll
        for (int g = 0; g < 2; g++) {
            float4 v = valid ? *(const float4*)&gsrc[gbase + rkg * 8 + g * 4]
                             : make_float4(0.f, 0.f, 0.f, 0.f);
            sr0[(rkg * 8 + g * 4 + 0) * 68] = v.x;
            sr0[(rkg * 8 + g * 4 + 1) * 68] = v.y;
            sr0[(rkg * 8 + g * 4 + 2) * 68] = v.z;
            sr0[(rkg * 8 + g * 4 + 3) * 68] = v.w;
        }
    }

    int nch = C >> 4;
    for (int ch = 0; ch < nch; ch++) {
        __syncthreads();
        int buf = ch & 1;

        float4 n0 = make_float4(0.f, 0.f, 0.f, 0.f);
        float4 n1 = make_float4(0.f, 0.f, 0.f, 0.f);
        float4 n2 = make_float4(0.f, 0.f, 0.f, 0.f);
        float4 n3 = make_float4(0.f, 0.f, 0.f, 0.f);
        if (ch + 1 < nch && valid) {
            size_t o = gbase + (size_t)(ch + 1) * 16;
            if (!isR) {
                n0 = *(const float4*)&gsrc[o];
                n1 = *(const float4*)&gsrc[o + 4];
                n2 = *(const float4*)&gsrc[o + 8];
                n3 = *(const float4*)&gsrc[o + 12];
            } else {
                n0 = *(const float4*)&gsrc[o + rkg * 8];
                n1 = *(const float4*)&gsrc[o + rkg * 8 + 4];
            }
        }

        #pragma unroll
        for (int kk = 0; kk < 16; kk++) {
            float4 q0 = *(const float4*)&qs[buf][kk][ty * 8];
            float4 q1 = *(const float4*)&qs[buf][kk][ty * 8 + 4];
            float4 rv = *(const float4*)&rs[buf][kk][tx * 4];
            acc[0][0] += q0.x * rv.x; acc[0][1] += q0.x * rv.y;
            acc[0][2] += q0.x * rv.z; acc[0][3] += q0.x * rv.w;
            acc[1][0] += q0.y * rv.x; acc[1][1] += q0.y * rv.y;
            acc[1][2] += q0.y * rv.z; acc[1][3] += q0.y * rv.w;
            acc[2][0] += q0.z * rv.x; acc[2][1] += q0.z * rv.y;
            acc[2][2] += q0.z * rv.z; acc[2][3] += q0.z * rv.w;
            acc[3][0] += q0.w * rv.x; acc[3][1] += q0.w * rv.y;
            acc[3][2] += q0.w * rv.z; acc[3][3] += q0.w * rv.w;
            acc[4][0] += q1.x * rv.x; acc[4][1] += q1.x * rv.y;
            acc[4][2] += q1.x * rv.z; acc[4][3] += q1.x * rv.w;
            acc[5][0] += q1.y * rv.x; acc[5][1] += q1.y * rv.y;
            acc[5][2] += q1.y * rv.z; acc[5][3] += q1.y * rv.w;
            acc[6][0] += q1.z * rv.x; acc[6][1] += q1.z * rv.y;
            acc[6][2] += q1.z * rv.z; acc[6][3] += q1.z * rv.w;
            acc[7][0] += q1.w * rv.x; acc[7][1] += q1.w * rv.y;
            acc[7][2] += q1.w * rv.z; acc[7][3] += q1.w * rv.w;
        }

        if (ch + 1 < nch) {
            if (!isR) {
                float* d = buf ? sq0 : sq1;
                d[0 * 132]  = n0.x; d[1 * 132]  = n0.y; d[2 * 132]  = n0.z; d[3 * 132]  = n0.w;
                d[4 * 132]  = n1.x; d[5 * 132]  = n1.y; d[6 * 132]  = n1.z; d[7 * 132]  = n1.w;
                d[8 * 132]  = n2.x; d[9 * 132]  = n2.y; d[10 * 132] = n2.z; d[11 * 132] = n2.w;
                d[12 * 132] = n3.x; d[13 * 132] = n3.y; d[14 * 132] = n3.z; d[15 * 132] = n3.w;
            } else {
                float* d = buf ? sr0 : sr1;
                d[(rkg * 8 + 0) * 68] = n0.x; d[(rkg * 8 + 1) * 68] = n0.y;
                d[(rkg * 8 + 2) * 68] = n0.z; d[(rkg * 8 + 3) * 68] = n0.w;
                d[(rkg * 8 + 4) * 68] = n1.x; d[(rkg * 8 + 5) * 68] = n1.y;
                d[(rkg * 8 + 6) * 68] = n1.z; d[(rkg * 8 + 7) * 68] = n1.w;
            }
        }
    }

    float* out = g_dot + ((size_t)l * NB + bt) * NRP + rt;
    #pragma unroll
    for (int i = 0; i < 8; i++) {
        *(float4*)&out[(size_t)(ty * 8 + i) * NRP + tx * 4] =
            make_float4(acc[i][0], acc[i][1], acc[i][2], acc[i][3]);
    }
}

// ---------------- kernel 4: extraction with uint mins + REDUX (proven R8 version) ----------------
__global__ void __launch_bounds__(256) select_kernel(const int* __restrict__ kp)
{
    int b = blockIdx.x;
    int l = blockIdx.y;
    int tid  = threadIdx.x;
    int warp = tid >> 5;
    int lane = tid & 31;

    __shared__ unsigned wv[2][8];
    __shared__ float topd[64];

    const float* dotp = g_dot + ((size_t)l * NB + b) * NRP;
    const float* r2p  = g_r2 + l * NR;
    float q2v = g_q2[l * NB + b];

    int base = tid * 8;
    float4 d0 = *(const float4*)&dotp[base];
    float4 d1 = *(const float4*)&dotp[base + 4];
    float dd[8] = {d0.x, d0.y, d0.z, d0.w, d1.x, d1.y, d1.z, d1.w};
    unsigned u[8];
    #pragma unroll
    for (int j = 0; j < 8; j++) {
        int r = base + j;
        float x = (r < NR) ? fmaxf(q2v + r2p[r] - 2.f * dd[j], 0.f) : FLT_MAX;
        u[j] = __float_as_uint(x);
    }

    int kk  = *kp;
    int kp1 = min(kk + 1, 64);

    for (int t = 0; t < kp1; t++) {
        unsigned a0 = min(u[0], u[1]), a1 = min(u[2], u[3]);
        unsigned a2 = min(u[4], u[5]), a3 = min(u[6], u[7]);
        unsigned lm = min(min(a0, a1), min(a2, a3));
        unsigned wm = __reduce_min_sync(0xffffffffu, lm);
        unsigned bal = __ballot_sync(0xffffffffu, lm == wm);
        bool leader = (lane == (__ffs(bal) - 1));
        int p = t & 1;
        if (lane == 0) wv[p][warp] = wm;
        __syncthreads();
        unsigned bm = wv[p][0]; int bw = 0;
        #pragma unroll
        for (int w = 1; w < 8; w++) {
            unsigned x = wv[p][w];
            if (x < bm) { bm = x; bw = w; }
        }
        if (tid == 0) topd[t] = __uint_as_float(bm);
        if (warp == bw && leader) {
            bool done = false;
            #pragma unroll
            for (int j = 0; j < 8; j++)
                if (!done && u[j] == wm) { u[j] = 0xFFFFFFFFu; done = true; }
        }
    }
    __syncthreads();

    if (warp == 0) {
        float dk = sqrtf(topd[kp1 - 1]);
        float s = 0.f;
        for (int i = lane; i < kp1; i += 32)
            if (i >= 1) s += logf(sqrtf(topd[i]) / dk);
        #pragma unroll
        for (int o = 16; o > 0; o >>= 1) s += __shfl_xor_sync(0xffffffffu, s, o);
        if (lane == 0) g_lid[b * 4 + l] = -(float)kk / s;
    }
}

// ---------------- kernel 5: linear head + sigmoid ----------------
__global__ void final_kernel(const float* __restrict__ w,
                             const float* __restrict__ bb,
                             float* __restrict__ out)
{
    int b = threadIdx.x;
    float z = bb[0];
    #pragma unroll
    for (int j = 0; j < 4; j++) z += g_lid[b * 4 + j] * w[j];
    out[b] = 1.f / (1.f + expf(-z));
}

// ---------------- launch ----------------
extern "C" void kernel_launch(void* const* d_in, const int* in_sizes, int n_in,
                              void* d_out, int out_size)
{
    const float* feat[4] = {0, 0, 0, 0};
    const float* ref[4]  = {0, 0, 0, 0};
    const float* rw = 0;
    const float* rb = 0;
    const int*   kp = 0;
    int ones = 0;
    for (int i = 0; i < n_in; i++) {
        switch (in_sizes[i]) {
            case 51380224: feat[0] = (const float*)d_in[i]; break;
            case 25690112: feat[1] = (const float*)d_in[i]; break;
            case 12845056: feat[2] = (const float*)d_in[i]; break;
            case 6422528:  feat[3] = (const float*)d_in[i]; break;
            case 128000:   ref[0]  = (const float*)d_in[i]; break;
            case 256000:   ref[1]  = (const float*)d_in[i]; break;
            case 512000:   ref[2]  = (const float*)d_in[i]; break;
            case 1024000:  ref[3]  = (const float*)d_in[i]; break;
            case 4:        rw      = (const float*)d_in[i]; break;
            case 1:
                if (ones++ == 0) rb = (const float*)d_in[i];
                else             kp = (const int*)d_in[i];
                break;
            default: break;
        }
    }

    static const int HW[4]    = {3136, 784, 196, 49};
    static const int QOFF[4]  = {0, 16384, 49152, 114688};
    static const int ROWS[4]  = {16384, 32768, 65536, 131072};

    // pools on default stream, smallest layer first (earliest gemm start);
    // record an event after each so its gemm can fork onto the side stream
    for (int i = 0; i < 4; i++) {
        int l = 3 - i;   // 3, 2, 1, 0
        pool_layer_kernel<<<ROWS[l] / 8, 256>>>(
            feat[l], HW[l], QOFF[l], ROWS[l], 1.f / (float)HW[l], (HW[l] & 3) == 0);
        cudaEventRecord(g_ov.evp[l], 0);
    }

    // norms after all pools (same stream)
    norms_kernel<<<1128, 256>>>(ref[0], ref[1], ref[2], ref[3]);

    // gemms on side stream, each gated on its layer's pool
    dim3 gg(NRP / 64, NB / 128);
    dim3 bt(16, 16);
    for (int i = 0; i < 4; i++) {
        int l = 3 - i;
        cudaStreamWaitEvent(g_ov.side, g_ov.evp[l], 0);
        dist_gemm_kernel<<<gg, bt, 0, g_ov.side>>>(ref[l], l);
    }
    cudaEventRecord(g_ov.evb, g_ov.side);

    // join side stream back into default before select
    cudaStreamWaitEvent(0, g_ov.evb, 0);

    dim3 gs(NB, 4);
    select_kernel<<<gs, 256>>>(kp);

    final_kernel<<<1, 256>>>(rw, rb, (float*)d_out);
}

// round 13
// speedup vs baseline: 1.1756x; 1.1756x over previous
#include <cuda_runtime.h>
#include <math.h>
#include <float.h>

// layers: C = {64,128,256,512}, HW = {3136,784,196,49}, B=256, R=2000
#define NB 256
#define NR 2000
#define NRP 2048

__constant__ int c_C[4]    = {64, 128, 256, 512};
__constant__ int c_HW[4]   = {3136, 784, 196, 49};
__constant__ int c_qoff[4] = {0, 16384, 49152, 114688};

// scratch (static device globals; no allocation)
__device__ __align__(16) float g_fq[245760];        // pooled queries
__device__ __align__(16) float g_dot[4 * NB * NRP]; // q . ref^T, padded
__device__ float g_r2[4 * NR];
__device__ float g_q2[4 * NB];
__device__ float g_lid[NB * 4];

// ---- packed fp32x2 helpers (sm_103a FFMA2) ----
__device__ __forceinline__ unsigned long long pack2dup(float a) {
    unsigned long long r;
    asm("mov.b64 %0, {%1, %1};" : "=l"(r) : "f"(a));
    return r;
}
__device__ __forceinline__ void ffma2(unsigned long long& d,
                                      unsigned long long a,
                                      unsigned long long b) {
    asm("fma.rn.f32x2 %0, %1, %2, %0;" : "+l"(d) : "l"(a), "l"(b));
}
__device__ __forceinline__ void unpack2(float& lo, float& hi, unsigned long long v) {
    asm("mov.b64 {%0, %1}, %2;" : "=f"(lo), "=f"(hi) : "l"(v));
}

// ---------------- kernel 1: spatial mean pooling (proven R8 version) ----------------
__global__ void __launch_bounds__(256) pool_kernel(
    const float* __restrict__ f0, const float* __restrict__ f1,
    const float* __restrict__ f2, const float* __restrict__ f3)
{
    int gw   = (blockIdx.x * 256 + threadIdx.x) >> 5;
    int lane = threadIdx.x & 31;
    if (gw >= 245760) return;

    int l, base;
    if      (gw < 16384)  { l = 0; base = 0; }
    else if (gw < 49152)  { l = 1; base = 16384; }
    else if (gw < 114688) { l = 2; base = 49152; }
    else                  { l = 3; base = 114688; }
    int row = gw - base;
    const float* f = (l == 0) ? f0 : (l == 1) ? f1 : (l == 2) ? f2 : f3;
    int HW = c_HW[l];
    const float* src = f + (size_t)row * HW;

    float s = 0.f;
    if (l < 3) {
        const float4* s4 = (const float4*)src;
        int n4 = HW >> 2;
        #pragma unroll 4
        for (int i = lane; i < n4; i += 32) {
            float4 v = s4[i];
            s += (v.x + v.y) + (v.z + v.w);
        }
    } else {
        #pragma unroll 2
        for (int i = lane; i < HW; i += 32) s += src[i];
    }
    #pragma unroll
    for (int o = 16; o > 0; o >>= 1) s += __shfl_xor_sync(0xffffffffu, s, o);
    if (lane == 0) g_fq[c_qoff[l] + row] = s / (float)HW;
}

// ---------------- kernel 2: squared norms (proven) ----------------
__global__ void __launch_bounds__(256) norms_kernel(
    const float* __restrict__ r0, const float* __restrict__ r1,
    const float* __restrict__ r2, const float* __restrict__ r3)
{
    int gw   = (blockIdx.x * 256 + threadIdx.x) >> 5;
    int lane = threadIdx.x & 31;
    if (gw >= 9024) return;

    const float* src;
    float* out;
    int C;
    if (gw < 8000) {
        int l = gw / NR, row = gw % NR;
        const float* rp = (l == 0) ? r0 : (l == 1) ? r1 : (l == 2) ? r2 : r3;
        C = c_C[l];
        src = rp + (size_t)row * C;
        out = g_r2 + l * NR + row;
    } else {
        int idx = gw - 8000;
        int l = idx >> 8, row = idx & 255;
        C = c_C[l];
        src = g_fq + c_qoff[l] + (size_t)row * C;
        out = g_q2 + l * NB + row;
    }
    float s = 0.f;
    const float4* s4 = (const float4*)src;
    int n4 = C >> 2;
    #pragma unroll 4
    for (int i = lane; i < n4; i += 32) {
        float4 v = s4[i];
        s += v.x * v.x + v.y * v.y + v.z * v.z + v.w * v.w;
    }
    #pragma unroll
    for (int o = 16; o > 0; o >>= 1) s += __shfl_xor_sync(0xffffffffu, s, o);
    if (lane == 0) *out = s;
}

// ---------------- kernel 3: 128x64 tile, FFMA2 inner loop ----------------
__global__ void __launch_bounds__(256) dist_gemm_kernel(
    const float* __restrict__ r0, const float* __restrict__ r1,
    const float* __restrict__ r2, const float* __restrict__ r3)
{
    int l = 3 - blockIdx.z;     // heavy layers first -> short tail
    int C = c_C[l];
    const float* ref = (l == 0) ? r0 : (l == 1) ? r1 : (l == 2) ? r2 : r3;
    const float* q   = g_fq + c_qoff[l];

    int bt = blockIdx.y << 7;   // batch tile (128)
    int rt = blockIdx.x << 6;   // ref tile (64)

    __shared__ __align__(16) float qs[2][16][132];
    __shared__ __align__(16) float rs[2][16][68];

    int tx = threadIdx.x;   // 0..15 -> ref cols tx*4
    int ty = threadIdx.y;   // 0..15 -> batch rows ty*8..+7
    int tid = ty * 16 + tx;

    int isR  = tid >> 7;
    int qrow = tid & 127;
    int rrow = (tid & 127) >> 1;
    int rkg  = tid & 1;

    const float* gsrc;
    size_t gbase;
    int valid;
    if (isR) {
        int rr = rt + rrow;
        valid = (rr < NR);
        gbase = (size_t)(valid ? rr : 0) * C;
        gsrc  = ref;
    } else {
        valid = 1;
        gbase = (size_t)(bt + qrow) * C;
        gsrc  = q;
    }
    float* sq0 = &qs[0][0][0] + qrow;
    float* sq1 = &qs[1][0][0] + qrow;
    float* sr0 = &rs[0][0][0] + rrow;
    float* sr1 = &rs[1][0][0] + rrow;

    // acc2[p][j]: row pair (ty*8+2p, ty*8+2p+1) x ref col (rt + tx*4 + j)
    unsigned long long acc2[4][4];
    #pragma unroll
    for (int i = 0; i < 4; i++)
        #pragma unroll
        for (int j = 0; j < 4; j++) acc2[i][j] = 0ULL;

    // prologue: chunk 0 -> buffer 0
    if (!isR) {
        #pragma unroll
        for (int g = 0; g < 4; g++) {
            float4 v = *(const float4*)&gsrc[gbase + g * 4];
            sq0[(g * 4 + 0) * 132] = v.x;
            sq0[(g * 4 + 1) * 132] = v.y;
            sq0[(g * 4 + 2) * 132] = v.z;
            sq0[(g * 4 + 3) * 132] = v.w;
        }
    } else {
        #pragma unroll
        for (int g = 0; g < 2; g++) {
            float4 v = valid ? *(const float4*)&gsrc[gbase + rkg * 8 + g * 4]
                             : make_float4(0.f, 0.f, 0.f, 0.f);
            sr0[(rkg * 8 + g * 4 + 0) * 68] = v.x;
            sr0[(rkg * 8 + g * 4 + 1) * 68] = v.y;
            sr0[(rkg * 8 + g * 4 + 2) * 68] = v.z;
            sr0[(rkg * 8 + g * 4 + 3) * 68] = v.w;
        }
    }

    int nch = C >> 4;
    for (int ch = 0; ch < nch; ch++) {
        __syncthreads();
        int buf = ch & 1;

        float4 n0 = make_float4(0.f, 0.f, 0.f, 0.f);
        float4 n1 = make_float4(0.f, 0.f, 0.f, 0.f);
        float4 n2 = make_float4(0.f, 0.f, 0.f, 0.f);
        float4 n3 = make_float4(0.f, 0.f, 0.f, 0.f);
        if (ch + 1 < nch && valid) {
            size_t o = gbase + (size_t)(ch + 1) * 16;
            if (!isR) {
                n0 = *(const float4*)&gsrc[o];
                n1 = *(const float4*)&gsrc[o + 4];
                n2 = *(const float4*)&gsrc[o + 8];
                n3 = *(const float4*)&gsrc[o + 12];
            } else {
                n0 = *(const float4*)&gsrc[o + rkg * 8];
                n1 = *(const float4*)&gsrc[o + rkg * 8 + 4];
            }
        }

        // compute chunk ch: 16 k-steps x (16 FFMA2 = 32 FMA)
        #pragma unroll
        for (int kk = 0; kk < 16; kk++) {
            // q row-pairs load directly as 2x uint64 (pairs adjacent in smem)
            ulonglong2 qa = *(const ulonglong2*)&qs[buf][kk][ty * 8];
            ulonglong2 qb = *(const ulonglong2*)&qs[buf][kk][ty * 8 + 4];
            float4 rv = *(const float4*)&rs[buf][kk][tx * 4];
            unsigned long long rp0 = pack2dup(rv.x);
            unsigned long long rp1 = pack2dup(rv.y);
            unsigned long long rp2 = pack2dup(rv.z);
            unsigned long long rp3 = pack2dup(rv.w);
            ffma2(acc2[0][0], qa.x, rp0); ffma2(acc2[0][1], qa.x, rp1);
            ffma2(acc2[0][2], qa.x, rp2); ffma2(acc2[0][3], qa.x, rp3);
            ffma2(acc2[1][0], qa.y, rp0); ffma2(acc2[1][1], qa.y, rp1);
            ffma2(acc2[1][2], qa.y, rp2); ffma2(acc2[1][3], qa.y, rp3);
            ffma2(acc2[2][0], qb.x, rp0); ffma2(acc2[2][1], qb.x, rp1);
            ffma2(acc2[2][2], qb.x, rp2); ffma2(acc2[2][3], qb.x, rp3);
            ffma2(acc2[3][0], qb.y, rp0); ffma2(acc2[3][1], qb.y, rp1);
            ffma2(acc2[3][2], qb.y, rp2); ffma2(acc2[3][3], qb.y, rp3);
        }

        if (ch + 1 < nch) {
            if (!isR) {
                float* d = buf ? sq0 : sq1;
                d[0 * 132]  = n0.x; d[1 * 132]  = n0.y; d[2 * 132]  = n0.z; d[3 * 132]  = n0.w;
                d[4 * 132]  = n1.x; d[5 * 132]  = n1.y; d[6 * 132]  = n1.z; d[7 * 132]  = n1.w;
                d[8 * 132]  = n2.x; d[9 * 132]  = n2.y; d[10 * 132] = n2.z; d[11 * 132] = n2.w;
                d[12 * 132] = n3.x; d[13 * 132] = n3.y; d[14 * 132] = n3.z; d[15 * 132] = n3.w;
            } else {
                float* d = buf ? sr0 : sr1;
                d[(rkg * 8 + 0) * 68] = n0.x; d[(rkg * 8 + 1) * 68] = n0.y;
                d[(rkg * 8 + 2) * 68] = n0.z; d[(rkg * 8 + 3) * 68] = n0.w;
                d[(rkg * 8 + 4) * 68] = n1.x; d[(rkg * 8 + 5) * 68] = n1.y;
                d[(rkg * 8 + 6) * 68] = n1.z; d[(rkg * 8 + 7) * 68] = n1.w;
            }
        }
    }

    float* out = g_dot + ((size_t)l * NB + bt) * NRP + rt;
    #pragma unroll
    for (int p = 0; p < 4; p++) {
        float lo0, hi0, lo1, hi1, lo2, hi2, lo3, hi3;
        unpack2(lo0, hi0, acc2[p][0]);
        unpack2(lo1, hi1, acc2[p][1]);
        unpack2(lo2, hi2, acc2[p][2]);
        unpack2(lo3, hi3, acc2[p][3]);
        *(float4*)&out[(size_t)(ty * 8 + 2 * p) * NRP + tx * 4] =
            make_float4(lo0, lo1, lo2, lo3);
        *(float4*)&out[(size_t)(ty * 8 + 2 * p + 1) * NRP + tx * 4] =
            make_float4(hi0, hi1, hi2, hi3);
    }
}

// ---------------- kernel 4: extraction with uint mins + REDUX (proven R8) ----------------
__global__ void __launch_bounds__(256) select_kernel(const int* __restrict__ kp)
{
    int b = blockIdx.x;
    int l = blockIdx.y;
    int tid  = threadIdx.x;
    int warp = tid >> 5;
    int lane = tid & 31;

    __shared__ unsigned wv[2][8];
    __shared__ float topd[64];

    const float* dotp = g_dot + ((size_t)l * NB + b) * NRP;
    const float* r2p  = g_r2 + l * NR;
    float q2v = g_q2[l * NB + b];

    int base = tid * 8;
    float4 d0 = *(const float4*)&dotp[base];
    float4 d1 = *(const float4*)&dotp[base + 4];
    float dd[8] = {d0.x, d0.y, d0.z, d0.w, d1.x, d1.y, d1.z, d1.w};
    unsigned u[8];
    #pragma unroll
    for (int j = 0; j < 8; j++) {
        int r = base + j;
        float x = (r < NR) ? fmaxf(q2v + r2p[r] - 2.f * dd[j], 0.f) : FLT_MAX;
        u[j] = __float_as_uint(x);
    }

    int kk  = *kp;
    int kp1 = min(kk + 1, 64);

    for (int t = 0; t < kp1; t++) {
        unsigned a0 = min(u[0], u[1]), a1 = min(u[2], u[3]);
        unsigned a2 = min(u[4], u[5]), a3 = min(u[6], u[7]);
        unsigned lm = min(min(a0, a1), min(a2, a3));
        unsigned wm = __reduce_min_sync(0xffffffffu, lm);
        unsigned bal = __ballot_sync(0xffffffffu, lm == wm);
        bool leader = (lane == (__ffs(bal) - 1));
        int p = t & 1;
        if (lane == 0) wv[p][warp] = wm;
        __syncthreads();
        unsigned bm = wv[p][0]; int bw = 0;
        #pragma unroll
        for (int w = 1; w < 8; w++) {
            unsigned x = wv[p][w];
            if (x < bm) { bm = x; bw = w; }
        }
        if (tid == 0) topd[t] = __uint_as_float(bm);
        if (warp == bw && leader) {
            bool done = false;
            #pragma unroll
            for (int j = 0; j < 8; j++)
                if (!done && u[j] == wm) { u[j] = 0xFFFFFFFFu; done = true; }
        }
    }
    __syncthreads();

    if (warp == 0) {
        float dk = sqrtf(topd[kp1 - 1]);
        float s = 0.f;
        for (int i = lane; i < kp1; i += 32)
            if (i >= 1) s += logf(sqrtf(topd[i]) / dk);
        #pragma unroll
        for (int o = 16; o > 0; o >>= 1) s += __shfl_xor_sync(0xffffffffu, s, o);
        if (lane == 0) g_lid[b * 4 + l] = -(float)kk / s;
    }
}

// ---------------- kernel 5: linear head + sigmoid ----------------
__global__ void final_kernel(const float* __restrict__ w,
                             const float* __restrict__ bb,
                             float* __restrict__ out)
{
    int b = threadIdx.x;
    float z = bb[0];
    #pragma unroll
    for (int j = 0; j < 4; j++) z += g_lid[b * 4 + j] * w[j];
    out[b] = 1.f / (1.f + expf(-z));
}

// ---------------- launch (single stream, proven order) ----------------
extern "C" void kernel_launch(void* const* d_in, const int* in_sizes, int n_in,
                              void* d_out, int out_size)
{
    const float* feat[4] = {0, 0, 0, 0};
    const float* ref[4]  = {0, 0, 0, 0};
    const float* rw = 0;
    const float* rb = 0;
    const int*   kp = 0;
    int ones = 0;
    for (int i = 0; i < n_in; i++) {
        switch (in_sizes[i]) {
            case 51380224: feat[0] = (const float*)d_in[i]; break;
            case 25690112: feat[1] = (const float*)d_in[i]; break;
            case 12845056: feat[2] = (const float*)d_in[i]; break;
            case 6422528:  feat[3] = (const float*)d_in[i]; break;
            case 128000:   ref[0]  = (const float*)d_in[i]; break;
            case 256000:   ref[1]  = (const float*)d_in[i]; break;
            case 512000:   ref[2]  = (const float*)d_in[i]; break;
            case 1024000:  ref[3]  = (const float*)d_in[i]; break;
            case 4:        rw      = (const float*)d_in[i]; break;
            case 1:
                if (ones++ == 0) rb = (const float*)d_in[i];
                else             kp = (const int*)d_in[i];
                break;
            default: break;
        }
    }

    pool_kernel<<<30720, 256>>>(feat[0], feat[1], feat[2], feat[3]);
    norms_kernel<<<1128, 256>>>(ref[0], ref[1], ref[2], ref[3]);

    dim3 gg(NRP / 64, NB / 128, 4);  // (32, 2, 4) = 256 blocks; z reversed inside
    dim3 bt(16, 16);
    dist_gemm_kernel<<<gg, bt>>>(ref[0], ref[1], ref[2], ref[3]);

    dim3 gs(NB, 4);
    select_kernel<<<gs, 256>>>(kp);

    final_kernel<<<1, 256>>>(rw, rb, (float*)d_out);
}